// round 4
// baseline (speedup 1.0000x reference)
#include <cuda_runtime.h>
#include <cuda_bf16.h>

#define N_USER 50000
#define N_ITEM 100000
#define N_TOT  150000
#define D      64
#define NNZ    2400000
#define B_SZ   4096
#define N_LAYERS 3

#define SCAN_B 1024
#define SCAN_NBLK ((N_TOT + SCAN_B - 1) / SCAN_B)   // 147

#define ROWS_PER_BLK 64
#define CHUNK 16
#define NCHUNK (ROWS_PER_BLK / CHUNK)               // 4
#define LBLK ((N_TOT + ROWS_PER_BLK - 1) / ROWS_PER_BLK)  // 2344

// ---------------- device scratch (allocation-free rule) ----------------
__device__ float g_E0[N_TOT * D];         // ego ping
__device__ float g_E1[N_TOT * D];         // ego pong
__device__ float g_all[N_TOT * 4 * D];    // [ego0 | norm1 | norm2 | norm3]
__device__ int   g_cnt[N_TOT];
__device__ int   g_rowptr[N_TOT + 1];
__device__ int   g_cur[N_TOT];
__device__ int   g_bsum[SCAN_NBLK + 1];
__device__ int2  g_csr[NNZ];              // packed (col, val-bits)

// ---------------------------------------------------------------------------
__global__ void init_kernel(const float* __restrict__ user_emb,
                            const float* __restrict__ item_emb) {
    int i = blockIdx.x * blockDim.x + threadIdx.x;
    if (i >= N_TOT * D) return;
    float v = (i < N_USER * D) ? user_emb[i] : item_emb[i - N_USER * D];
    g_E0[i] = v;
    int row = i >> 6, col = i & 63;
    g_all[row * (4 * D) + col] = v;
    if (col == 0) g_cnt[row] = 0;
}

// ---------------------------------------------------------------------------
// CSR build
// ---------------------------------------------------------------------------
__global__ void hist_kernel(const int* __restrict__ rows) {
    int i = blockIdx.x * blockDim.x + threadIdx.x;
    if (i < NNZ) atomicAdd(&g_cnt[rows[i]], 1);
}

__global__ void scan1_kernel() {
    __shared__ int s[SCAN_B];
    int tid = threadIdx.x;
    int gid = blockIdx.x * SCAN_B + tid;
    int v = (gid < N_TOT) ? g_cnt[gid] : 0;
    s[tid] = v;
    __syncthreads();
    #pragma unroll
    for (int off = 1; off < SCAN_B; off <<= 1) {
        int t = (tid >= off) ? s[tid - off] : 0;
        __syncthreads();
        s[tid] += t;
        __syncthreads();
    }
    if (gid < N_TOT) g_rowptr[gid] = s[tid] - v;
    if (tid == SCAN_B - 1) g_bsum[blockIdx.x] = s[tid];
}

__global__ void scan2_kernel() {
    __shared__ int s[256];
    int tid = threadIdx.x;
    int v = (tid < SCAN_NBLK) ? g_bsum[tid] : 0;
    s[tid] = v;
    __syncthreads();
    #pragma unroll
    for (int off = 1; off < 256; off <<= 1) {
        int t = (tid >= off) ? s[tid - off] : 0;
        __syncthreads();
        s[tid] += t;
        __syncthreads();
    }
    if (tid < SCAN_NBLK) g_bsum[tid] = s[tid] - v;
}

__global__ void scan3_kernel() {
    int gid = blockIdx.x * SCAN_B + threadIdx.x;
    if (gid < N_TOT) {
        g_rowptr[gid] += g_bsum[blockIdx.x];
        g_cur[gid] = 0;
    }
    if (gid == 0) g_rowptr[N_TOT] = NNZ;
}

__global__ void scatter_kernel(const float* __restrict__ vals,
                               const int*   __restrict__ rows,
                               const int*   __restrict__ cols) {
    int i = blockIdx.x * blockDim.x + threadIdx.x;
    if (i >= NNZ) return;
    int r = rows[i];
    int pos = g_rowptr[r] + atomicAdd(&g_cur[r], 1);
    g_csr[pos] = make_int2(cols[i], __float_as_int(vals[i]));
}

// ---------------------------------------------------------------------------
// Producer: fill one chunk (16 rows) of sA = [L+E | L*E] (16 x 128).
// 128 producer threads: 16 threads/row, 8 rows per pass, 2 passes.
// ---------------------------------------------------------------------------
__device__ __forceinline__ void fill_chunk(float* __restrict__ sAbuf,
                                           int chunkRowBase,
                                           int pt,
                                           const float* __restrict__ ego_in) {
    int rsub = pt >> 4;            // 0..7
    int c    = (pt & 15) << 2;     // float4 col offset
    #pragma unroll
    for (int pass = 0; pass < 2; pass++) {
        int rl  = pass * 8 + rsub;        // 0..15
        int row = chunkRowBase + rl;
        float4 acc = make_float4(0.f, 0.f, 0.f, 0.f);
        float4 e   = make_float4(0.f, 0.f, 0.f, 0.f);
        if (row < N_TOT) {
            int s0 = g_rowptr[row];
            int e0 = g_rowptr[row + 1];
            int j = s0;
            for (; j + 4 <= e0; j += 4) {
                int2 a = g_csr[j];
                int2 b = g_csr[j + 1];
                int2 cc = g_csr[j + 2];
                int2 dd = g_csr[j + 3];
                float4 va = __ldg((const float4*)&ego_in[a.x * D + c]);
                float4 vb = __ldg((const float4*)&ego_in[b.x * D + c]);
                float4 vc = __ldg((const float4*)&ego_in[cc.x * D + c]);
                float4 vd = __ldg((const float4*)&ego_in[dd.x * D + c]);
                float fa = __int_as_float(a.y);
                float fb = __int_as_float(b.y);
                float fc = __int_as_float(cc.y);
                float fd = __int_as_float(dd.y);
                acc.x += fa * va.x + fb * vb.x + fc * vc.x + fd * vd.x;
                acc.y += fa * va.y + fb * vb.y + fc * vc.y + fd * vd.y;
                acc.z += fa * va.z + fb * vb.z + fc * vc.z + fd * vd.z;
                acc.w += fa * va.w + fb * vb.w + fc * vc.w + fd * vd.w;
            }
            for (; j < e0; j++) {
                int2 a = g_csr[j];
                float4 va = __ldg((const float4*)&ego_in[a.x * D + c]);
                float fa = __int_as_float(a.y);
                acc.x += fa * va.x; acc.y += fa * va.y;
                acc.z += fa * va.z; acc.w += fa * va.w;
            }
            e = *(const float4*)&ego_in[row * D + c];
        }
        *(float4*)&sAbuf[rl * 128 + c] =
            make_float4(acc.x + e.x, acc.y + e.y, acc.z + e.z, acc.w + e.w);
        *(float4*)&sAbuf[rl * 128 + 64 + c] =
            make_float4(acc.x * e.x, acc.y * e.y, acc.z * e.z, acc.w * e.w);
    }
}

// ---------------------------------------------------------------------------
// FUSED warp-specialized layer kernel.
//   warps 0-3 (tid<128): CSR-gather producers -> sA chunks (double buffered)
//   warps 4-7: GEMM consumers + epilogue (bias, leaky-relu, norm, stores)
// ---------------------------------------------------------------------------
__global__ void __launch_bounds__(256)
fused_layer_kernel(const float* __restrict__ ego_in,
                   float*       __restrict__ ego_out,
                   const float* __restrict__ Wgc,
                   const float* __restrict__ Wbi,
                   const float* __restrict__ bb,
                   int layer) {
    __shared__ float sA[2][CHUNK * 128];   // double-buffered [row][k]
    __shared__ float sW[128 * 64];         // [k][n] (Wgc ; Wbi)

    int tid = threadIdx.x;
    int rowBase = blockIdx.x * ROWS_PER_BLK;
    bool is_prod = (tid < 128);

    if (is_prod) {
        // producers: fill chunk 0 into buffer 0
        fill_chunk(sA[0], rowBase, tid, ego_in);
    } else {
        // consumers: stage W' (8192 floats = 2048 float4, 16 per thread)
        int ct = tid - 128;
        const float4* wg4 = (const float4*)Wgc;
        const float4* wb4 = (const float4*)Wbi;
        float4* sW4 = (float4*)sW;
        #pragma unroll
        for (int i = 0; i < 8; i++) sW4[ct + i * 128] = wg4[ct + i * 128];
        #pragma unroll
        for (int i = 0; i < 8; i++) sW4[1024 + ct + i * 128] = wb4[ct + i * 128];
    }
    __syncthreads();

    // consumer thread geometry
    int ct = tid - 128;
    int ty = ct >> 4;       // 0..7 -> chunk rows 2ty, 2ty+1
    int tx = ct & 15;       // cols 4tx..4tx+3
    float4 b4 = is_prod ? make_float4(0.f, 0.f, 0.f, 0.f)
                        : *(const float4*)&bb[4 * tx];

    #pragma unroll
    for (int s = 0; s < NCHUNK; s++) {
        if (is_prod) {
            if (s + 1 < NCHUNK)
                fill_chunk(sA[(s + 1) & 1], rowBase + (s + 1) * CHUNK, tid, ego_in);
        } else {
            const float* buf = sA[s & 1];
            const float* pa0 = &buf[(2 * ty) * 128];
            const float* pa1 = pa0 + 128;

            float acc00 = 0.f, acc01 = 0.f, acc02 = 0.f, acc03 = 0.f;
            float acc10 = 0.f, acc11 = 0.f, acc12 = 0.f, acc13 = 0.f;

            #pragma unroll
            for (int k4 = 0; k4 < 32; k4++) {
                float4 A0 = *(const float4*)&pa0[k4 * 4];
                float4 A1 = *(const float4*)&pa1[k4 * 4];
                const float* wp = &sW[(k4 * 4) * 64 + 4 * tx];
                float4 w0 = *(const float4*)(wp);
                float4 w1 = *(const float4*)(wp + 64);
                float4 w2 = *(const float4*)(wp + 128);
                float4 w3 = *(const float4*)(wp + 192);
                acc00 += A0.x * w0.x; acc01 += A0.x * w0.y; acc02 += A0.x * w0.z; acc03 += A0.x * w0.w;
                acc10 += A1.x * w0.x; acc11 += A1.x * w0.y; acc12 += A1.x * w0.z; acc13 += A1.x * w0.w;
                acc00 += A0.y * w1.x; acc01 += A0.y * w1.y; acc02 += A0.y * w1.z; acc03 += A0.y * w1.w;
                acc10 += A1.y * w1.x; acc11 += A1.y * w1.y; acc12 += A1.y * w1.z; acc13 += A1.y * w1.w;
                acc00 += A0.z * w2.x; acc01 += A0.z * w2.y; acc02 += A0.z * w2.z; acc03 += A0.z * w2.w;
                acc10 += A1.z * w2.x; acc11 += A1.z * w2.y; acc12 += A1.z * w2.z; acc13 += A1.z * w2.w;
                acc00 += A0.w * w3.x; acc01 += A0.w * w3.y; acc02 += A0.w * w3.z; acc03 += A0.w * w3.w;
                acc10 += A1.w * w3.x; acc11 += A1.w * w3.y; acc12 += A1.w * w3.z; acc13 += A1.w * w3.w;
            }

            // reference adds b_bi to BOTH branches -> 2*b
            float x0 = acc00 + 2.f * b4.x, x1 = acc01 + 2.f * b4.y;
            float x2 = acc02 + 2.f * b4.z, x3 = acc03 + 2.f * b4.w;
            float y0 = acc10 + 2.f * b4.x, y1 = acc11 + 2.f * b4.y;
            float y2 = acc12 + 2.f * b4.z, y3 = acc13 + 2.f * b4.w;

            x0 = x0 > 0.f ? x0 : 0.01f * x0;  x1 = x1 > 0.f ? x1 : 0.01f * x1;
            x2 = x2 > 0.f ? x2 : 0.01f * x2;  x3 = x3 > 0.f ? x3 : 0.01f * x3;
            y0 = y0 > 0.f ? y0 : 0.01f * y0;  y1 = y1 > 0.f ? y1 : 0.01f * y1;
            y2 = y2 > 0.f ? y2 : 0.01f * y2;  y3 = y3 > 0.f ? y3 : 0.01f * y3;

            float ss0 = x0 * x0 + x1 * x1 + x2 * x2 + x3 * x3;
            float ss1 = y0 * y0 + y1 * y1 + y2 * y2 + y3 * y3;
            #pragma unroll
            for (int o = 8; o; o >>= 1) {
                ss0 += __shfl_xor_sync(0xffffffffu, ss0, o);
                ss1 += __shfl_xor_sync(0xffffffffu, ss1, o);
            }
            float inv0 = 1.0f / fmaxf(sqrtf(ss0), 1e-12f);
            float inv1 = 1.0f / fmaxf(sqrtf(ss1), 1e-12f);

            int r0 = rowBase + s * CHUNK + 2 * ty;
            int r1 = r0 + 1;
            int co = (layer + 1) * D + 4 * tx;
            if (r0 < N_TOT) {
                *(float4*)&ego_out[r0 * D + 4 * tx] = make_float4(x0, x1, x2, x3);
                *(float4*)&g_all[r0 * (4 * D) + co] =
                    make_float4(x0 * inv0, x1 * inv0, x2 * inv0, x3 * inv0);
            }
            if (r1 < N_TOT) {
                *(float4*)&ego_out[r1 * D + 4 * tx] = make_float4(y0, y1, y2, y3);
                *(float4*)&g_all[r1 * (4 * D) + co] =
                    make_float4(y0 * inv1, y1 * inv1, y2 * inv1, y3 * inv1);
            }
        }
        __syncthreads();
    }
}

// ---------------------------------------------------------------------------
__global__ void gather_kernel(const int* __restrict__ users,
                              const int* __restrict__ pos_items,
                              const int* __restrict__ neg_items,
                              float* __restrict__ out) {
    int idx = blockIdx.x * blockDim.x + threadIdx.x;  // 3*B*256
    if (idx >= 3 * B_SZ * (4 * D)) return;
    int which = idx / (B_SZ * 4 * D);
    int rem   = idx - which * (B_SZ * 4 * D);
    int b = rem >> 8;
    int c = rem & 255;
    int row;
    if (which == 0)      row = users[b];
    else if (which == 1) row = N_USER + pos_items[b];
    else                 row = N_USER + neg_items[b];
    out[idx] = g_all[row * (4 * D) + c];
}

// ---------------------------------------------------------------------------
extern "C" void kernel_launch(void* const* d_in, const int* in_sizes, int n_in,
                              void* d_out, int out_size) {
    const float* user_emb  = (const float*)d_in[0];
    const float* item_emb  = (const float*)d_in[1];
    const float* W_gc      = (const float*)d_in[2];
    const float* W_bi      = (const float*)d_in[3];
    const float* b_bi      = (const float*)d_in[4];
    const float* vals      = (const float*)d_in[5];
    const int*   rows      = (const int*)d_in[6];
    const int*   cols      = (const int*)d_in[7];
    const int*   users     = (const int*)d_in[8];
    const int*   pos_items = (const int*)d_in[9];
    const int*   neg_items = (const int*)d_in[10];
    float* out = (float*)d_out;

    init_kernel<<<(N_TOT * D + 255) / 256, 256>>>(user_emb, item_emb);

    hist_kernel<<<(NNZ + 255) / 256, 256>>>(rows);
    scan1_kernel<<<SCAN_NBLK, SCAN_B>>>();
    scan2_kernel<<<1, 256>>>();
    scan3_kernel<<<SCAN_NBLK, SCAN_B>>>();
    scatter_kernel<<<(NNZ + 255) / 256, 256>>>(vals, rows, cols);

    float* e0; float* e1;
    cudaGetSymbolAddress((void**)&e0, g_E0);
    cudaGetSymbolAddress((void**)&e1, g_E1);

    for (int k = 0; k < N_LAYERS; k++) {
        const float* in   = (k & 1) ? e1 : e0;
        float*       outp = (k & 1) ? e0 : e1;
        fused_layer_kernel<<<LBLK, 256>>>(in, outp,
                                          W_gc + k * D * D,
                                          W_bi + k * D * D,
                                          b_bi + k * D, k);
    }

    gather_kernel<<<(3 * B_SZ * 4 * D + 255) / 256, 256>>>(users, pos_items,
                                                           neg_items, out);
}